// round 5
// baseline (speedup 1.0000x reference)
#include <cuda_runtime.h>

typedef unsigned long long ull;

#define NN 50000
#define IN_CH 128
#define OUT_CH 64
#define HEADS 4
#define HC 256            // HEADS*OUT_CH
#define MAX_E 800000
#define MAX_TE (MAX_E + NN)
#define NEG_SLOPE 0.2f

// ---------------- scratch (allocation-free) ----------------
__device__ float    g_h[(size_t)NN * HC];        // 51.2 MB
__device__ float    g_asrc[NN * HEADS];
__device__ float    g_adst[NN * HEADS];
__device__ unsigned g_mu[NN * HEADS];
__device__ float    g_m[NN * HEADS];
__device__ float    g_den[NN * HEADS];
__device__ float    g_ex[(size_t)MAX_TE * HEADS]; // 13.6 MB

// ---------------- helpers ----------------
__device__ __forceinline__ unsigned enc_f(float f) {
    unsigned b = __float_as_uint(f);
    return (b & 0x80000000u) ? ~b : (b | 0x80000000u);
}
__device__ __forceinline__ float dec_f(unsigned u) {
    return (u & 0x80000000u) ? __uint_as_float(u & 0x7FFFFFFFu)
                             : __uint_as_float(~u);
}
__device__ __forceinline__ float lrelu(float v) {
    return v >= 0.f ? v : NEG_SLOPE * v;
}
__device__ __forceinline__ int clampN(int v, int N) {
    v = v < 0 ? 0 : v;
    return v >= N ? N - 1 : v;
}
__device__ __forceinline__ ull splat2(float x) {
    ull r;
    asm("mov.b64 %0, {%1, %1};" : "=l"(r) : "r"(__float_as_uint(x)));
    return r;
}
__device__ __forceinline__ void fma2(ull& d, ull a, ull b) {
    asm("fma.rn.f32x2 %0, %1, %2, %0;" : "+l"(d) : "l"(a), "l"(b));
}

// ---------------- K0: init out=bias, zero mu/den ----------------
__global__ void k_init(float* __restrict__ out, const float* __restrict__ bias,
                       int total_out, int nh) {
    int i = blockIdx.x * blockDim.x + threadIdx.x;
    if (i < total_out) out[i] = __ldg(&bias[i & (HC - 1)]);
    if (i < nh) { g_mu[i] = 0u; g_den[i] = 0.f; }
}

// ---------------- K1: h = x @ W  (fp32, packed f32x2 FFMA) ----------------
__global__ __launch_bounds__(256) void k_gemm(const float* __restrict__ x,
                                              const float* __restrict__ W,
                                              int N) {
    __shared__ float xs[64 * IN_CH];   // 32 KB
    const int tid = threadIdx.x;
    const int col_t = tid & 31;
    const int row_g = tid >> 5;
    const int block_row = blockIdx.x * 64;

    // load x tile (clamp OOB rows)
    const float4* x4 = (const float4*)x;
    float4* xs4 = (float4*)xs;
#pragma unroll
    for (int i = 0; i < 8; i++) {
        int idx = tid + 256 * i;          // float4 index in 64x32 tile
        int r = block_row + (idx >> 5);
        int rc = r < N ? r : N - 1;
        xs4[idx] = x4[(size_t)rc * 32 + (idx & 31)];
    }
    __syncthreads();

    ull acc[8][4];
#pragma unroll
    for (int i = 0; i < 8; i++)
#pragma unroll
        for (int j = 0; j < 4; j++) acc[i][j] = 0ull;

    const float* xrow = xs + row_g * 8 * IN_CH;
    const int wcol = col_t * 2;

#pragma unroll 4
    for (int k = 0; k < IN_CH; k++) {
        ull w0 = __ldg((const ull*)&W[k * HC + 0 * 64 + wcol]);
        ull w1 = __ldg((const ull*)&W[k * HC + 1 * 64 + wcol]);
        ull w2 = __ldg((const ull*)&W[k * HC + 2 * 64 + wcol]);
        ull w3 = __ldg((const ull*)&W[k * HC + 3 * 64 + wcol]);
#pragma unroll
        for (int i = 0; i < 8; i++) {
            ull xx = splat2(xrow[i * IN_CH + k]);   // warp-uniform broadcast LDS
            fma2(acc[i][0], xx, w0);
            fma2(acc[i][1], xx, w1);
            fma2(acc[i][2], xx, w2);
            fma2(acc[i][3], xx, w3);
        }
    }

#pragma unroll
    for (int i = 0; i < 8; i++) {
        int r = block_row + row_g * 8 + i;
        if (r < N) {
#pragma unroll
            for (int jj = 0; jj < 4; jj++)
                *(ull*)&g_h[(size_t)r * HC + jj * 64 + wcol] = acc[i][jj];
        }
    }
}

// ---------------- K2: per-node attention logits ----------------
__global__ void k_logits(const float* __restrict__ att_src,
                         const float* __restrict__ att_dst, int N) {
    int t = blockIdx.x * blockDim.x + threadIdx.x;
    if (t >= N * HEADS) return;
    int n = t >> 2, hh = t & 3;
    const float4* hv = (const float4*)(g_h + (size_t)n * HC + hh * OUT_CH);
    const float4* as = (const float4*)(att_src + hh * OUT_CH);
    const float4* ad = (const float4*)(att_dst + hh * OUT_CH);
    float s = 0.f, d = 0.f;
#pragma unroll
    for (int c = 0; c < 16; c++) {
        float4 h4 = hv[c];
        float4 a4 = __ldg(&as[c]);
        float4 b4 = __ldg(&ad[c]);
        s += h4.x * a4.x + h4.y * a4.y + h4.z * a4.z + h4.w * a4.w;
        d += h4.x * b4.x + h4.y * b4.y + h4.z * b4.z + h4.w * b4.w;
    }
    g_asrc[t] = s;
    g_adst[t] = d;
}

// ---------------- K3: segment max over dst (encoded atomicMax) ----------------
__global__ void k_edge_max(const int* __restrict__ ei, int E, int TE, int N) {
    int e = blockIdx.x * blockDim.x + threadIdx.x;
    if (e >= TE) return;
    int s, d;
    if (e < E) { s = clampN(__ldg(ei + e), N); d = clampN(__ldg(ei + E + e), N); }
    else       { s = d = e - E; }
    float4 as = *(const float4*)(g_asrc + (size_t)s * 4);
    float4 ad = *(const float4*)(g_adst + (size_t)d * 4);
    unsigned* mu = g_mu + (size_t)d * 4;
    atomicMax(mu + 0, enc_f(lrelu(as.x + ad.x)));
    atomicMax(mu + 1, enc_f(lrelu(as.y + ad.y)));
    atomicMax(mu + 2, enc_f(lrelu(as.z + ad.z)));
    atomicMax(mu + 3, enc_f(lrelu(as.w + ad.w)));
}

// ---------------- K4: decode max ----------------
__global__ void k_decode(int nh) {
    int i = blockIdx.x * blockDim.x + threadIdx.x;
    if (i < nh) g_m[i] = dec_f(g_mu[i]);
}

// ---------------- K5: ex = exp(e - m), denom += ex ----------------
__global__ void k_edge_exp(const int* __restrict__ ei, int E, int TE, int N) {
    int e = blockIdx.x * blockDim.x + threadIdx.x;
    if (e >= TE) return;
    int s, d;
    if (e < E) { s = clampN(__ldg(ei + e), N); d = clampN(__ldg(ei + E + e), N); }
    else       { s = d = e - E; }
    float4 as = *(const float4*)(g_asrc + (size_t)s * 4);
    float4 ad = *(const float4*)(g_adst + (size_t)d * 4);
    float4 m4 = *(const float4*)(g_m + (size_t)d * 4);
    float4 ex;
    ex.x = __expf(lrelu(as.x + ad.x) - m4.x);
    ex.y = __expf(lrelu(as.y + ad.y) - m4.y);
    ex.z = __expf(lrelu(as.z + ad.z) - m4.z);
    ex.w = __expf(lrelu(as.w + ad.w) - m4.w);
    *(float4*)(g_ex + (size_t)e * 4) = ex;
    float* den = g_den + (size_t)d * 4;
    atomicAdd(den + 0, ex.x);
    atomicAdd(den + 1, ex.y);
    atomicAdd(den + 2, ex.z);
    atomicAdd(den + 3, ex.w);
}

// ---------------- K6: out[dst] += alpha * h[src]  (warp per edge) ----------------
__global__ __launch_bounds__(256) void k_scatter(const int* __restrict__ ei,
                                                 float* __restrict__ out,
                                                 int E, int TE, int N) {
    int gw = (int)((blockIdx.x * (unsigned)blockDim.x + threadIdx.x) >> 5);
    if (gw >= TE) return;
    int lane = threadIdx.x & 31;
    int s, d;
    if (gw < E) { s = clampN(__ldg(ei + gw), N); d = clampN(__ldg(ei + E + gw), N); }
    else        { s = d = gw - E; }
    const float* hrow = g_h + (size_t)s * HC;
    float* orow = out + (size_t)d * HC;
#pragma unroll
    for (int it = 0; it < 2; it++) {
        int off = it * 128 + lane * 4;
        int hh = off >> 6;
        float alpha = __ldg(&g_ex[(size_t)gw * 4 + hh]) /
                      (__ldg(&g_den[(size_t)d * 4 + hh]) + 1e-16f);
        float4 hv = *(const float4*)(hrow + off);
        asm volatile("red.global.add.v4.f32 [%0], {%1, %2, %3, %4};"
                     :: "l"(orow + off),
                        "f"(hv.x * alpha), "f"(hv.y * alpha),
                        "f"(hv.z * alpha), "f"(hv.w * alpha)
                     : "memory");
    }
}

// ---------------- launch ----------------
extern "C" void kernel_launch(void* const* d_in, const int* in_sizes, int n_in,
                              void* d_out, int out_size) {
    const float* x       = (const float*)d_in[0];
    const int*   ei      = (const int*)d_in[1];     // int32 (JAX x64 disabled)
    const float* W       = (const float*)d_in[2];
    const float* att_src = (const float*)d_in[3];
    const float* att_dst = (const float*)d_in[4];
    const float* bias    = (const float*)d_in[5];
    float*       out     = (float*)d_out;

    const int N  = in_sizes[0] / IN_CH;   // 50000
    const int E  = in_sizes[1] / 2;       // 800000
    const int TE = E + N;                 // 850000 (self-loops appended)
    const int NH = N * HEADS;

    k_init<<<(N * HC + 255) / 256, 256>>>(out, bias, N * HC, NH);
    k_gemm<<<(N + 63) / 64, 256>>>(x, W, N);
    k_logits<<<(NH + 255) / 256, 256>>>(att_src, att_dst, N);
    k_edge_max<<<(TE + 255) / 256, 256>>>(ei, E, TE, N);
    k_decode<<<(NH + 255) / 256, 256>>>(NH);
    k_edge_exp<<<(TE + 255) / 256, 256>>>(ei, E, TE, N);
    long long scatter_threads = (long long)TE * 32;
    k_scatter<<<(unsigned)((scatter_threads + 255) / 256), 256>>>(ei, out, E, TE, N);
}

// round 6
// speedup vs baseline: 1.8124x; 1.8124x over previous
#include <cuda_runtime.h>

typedef unsigned long long ull;

#define NN 50000
#define IN_CH 128
#define OUT_CH 64
#define HEADS 4
#define HC 256            // HEADS*OUT_CH
#define MAX_E 800000
#define MAX_TE (MAX_E + NN)
#define NEG_SLOPE 0.2f

// ---------------- scratch (allocation-free) ----------------
__device__ float g_h[(size_t)NN * HC];        // 51.2 MB
__device__ float g_asrc[NN * HEADS];
__device__ float g_adst[NN * HEADS];
__device__ int   g_cnt[NN];                   // in-degree histogram
__device__ int   g_rowstart[NN + 1];          // CSR row pointers (by dst)
__device__ int   g_cursor[NN];                // fill cursors
__device__ int   g_blocksums[128];
__device__ int   g_col[MAX_TE];               // src per CSR slot

// ---------------- helpers ----------------
__device__ __forceinline__ float lrelu(float v) {
    return v >= 0.f ? v : NEG_SLOPE * v;
}
__device__ __forceinline__ int clampN(int v, int N) {
    v = v < 0 ? 0 : v;
    return v >= N ? N - 1 : v;
}
__device__ __forceinline__ ull splat2(float x) {
    ull r;
    asm("mov.b64 %0, {%1, %1};" : "=l"(r) : "r"(__float_as_uint(x)));
    return r;
}
__device__ __forceinline__ void fma2(ull& d, ull a, ull b) {
    asm("fma.rn.f32x2 %0, %1, %2, %0;" : "+l"(d) : "l"(a), "l"(b));
}

// ---------------- K0: init degree counters (1 = self-loop) ----------------
__global__ void k_setup(int N) {
    int i = blockIdx.x * blockDim.x + threadIdx.x;
    if (i < N) g_cnt[i] = 1;
}

// ---------------- K1: h = x @ W  (fp32, packed f32x2 FFMA) ----------------
__global__ __launch_bounds__(256) void k_gemm(const float* __restrict__ x,
                                              const float* __restrict__ W,
                                              int N) {
    __shared__ float xs[64 * IN_CH];   // 32 KB
    const int tid = threadIdx.x;
    const int col_t = tid & 31;
    const int row_g = tid >> 5;
    const int block_row = blockIdx.x * 64;

    const float4* x4 = (const float4*)x;
    float4* xs4 = (float4*)xs;
#pragma unroll
    for (int i = 0; i < 8; i++) {
        int idx = tid + 256 * i;
        int r = block_row + (idx >> 5);
        int rc = r < N ? r : N - 1;
        xs4[idx] = x4[(size_t)rc * 32 + (idx & 31)];
    }
    __syncthreads();

    ull acc[8][4];
#pragma unroll
    for (int i = 0; i < 8; i++)
#pragma unroll
        for (int j = 0; j < 4; j++) acc[i][j] = 0ull;

    const float* xrow = xs + row_g * 8 * IN_CH;
    const int wcol = col_t * 2;

#pragma unroll 4
    for (int k = 0; k < IN_CH; k++) {
        ull w0 = __ldg((const ull*)&W[k * HC + 0 * 64 + wcol]);
        ull w1 = __ldg((const ull*)&W[k * HC + 1 * 64 + wcol]);
        ull w2 = __ldg((const ull*)&W[k * HC + 2 * 64 + wcol]);
        ull w3 = __ldg((const ull*)&W[k * HC + 3 * 64 + wcol]);
#pragma unroll
        for (int i = 0; i < 8; i++) {
            ull xx = splat2(xrow[i * IN_CH + k]);
            fma2(acc[i][0], xx, w0);
            fma2(acc[i][1], xx, w1);
            fma2(acc[i][2], xx, w2);
            fma2(acc[i][3], xx, w3);
        }
    }

#pragma unroll
    for (int i = 0; i < 8; i++) {
        int r = block_row + row_g * 8 + i;
        if (r < N) {
#pragma unroll
            for (int jj = 0; jj < 4; jj++)
                *(ull*)&g_h[(size_t)r * HC + jj * 64 + wcol] = acc[i][jj];
        }
    }
}

// ---------------- K2: per-node attention logits ----------------
__global__ void k_logits(const float* __restrict__ att_src,
                         const float* __restrict__ att_dst, int N) {
    int t = blockIdx.x * blockDim.x + threadIdx.x;
    if (t >= N * HEADS) return;
    int n = t >> 2, hh = t & 3;
    const float4* hv = (const float4*)(g_h + (size_t)n * HC + hh * OUT_CH);
    const float4* as = (const float4*)(att_src + hh * OUT_CH);
    const float4* ad = (const float4*)(att_dst + hh * OUT_CH);
    float s = 0.f, d = 0.f;
#pragma unroll
    for (int c = 0; c < 16; c++) {
        float4 h4 = hv[c];
        float4 a4 = __ldg(&as[c]);
        float4 b4 = __ldg(&ad[c]);
        s += h4.x * a4.x + h4.y * a4.y + h4.z * a4.z + h4.w * a4.w;
        d += h4.x * b4.x + h4.y * b4.y + h4.z * b4.z + h4.w * b4.w;
    }
    g_asrc[t] = s;
    g_adst[t] = d;
}

// ---------------- K3: in-degree histogram over dst ----------------
__global__ void k_hist(const int* __restrict__ ei, int E, int N) {
    int e = blockIdx.x * blockDim.x + threadIdx.x;
    if (e >= E) return;
    int d = clampN(__ldg(ei + E + e), N);
    atomicAdd(&g_cnt[d], 1);
}

// ---------------- K4a/b/c: exclusive scan of g_cnt -> g_rowstart ----------------
__global__ void k_scan1(int n) {               // per-block sums
    __shared__ int sh[512];
    int i = blockIdx.x * 512 + threadIdx.x;
    sh[threadIdx.x] = (i < n) ? g_cnt[i] : 0;
    __syncthreads();
    for (int off = 256; off > 0; off >>= 1) {
        if (threadIdx.x < off) sh[threadIdx.x] += sh[threadIdx.x + off];
        __syncthreads();
    }
    if (threadIdx.x == 0) g_blocksums[blockIdx.x] = sh[0];
}

__global__ void k_scan2(int nb) {              // scan of block sums (1 block)
    __shared__ int sh[128];
    int t = threadIdx.x;
    int v = (t < nb) ? g_blocksums[t] : 0;
    sh[t] = v;
    __syncthreads();
    for (int off = 1; off < 128; off <<= 1) {
        int tmp = (t >= off) ? sh[t - off] : 0;
        __syncthreads();
        sh[t] += tmp;
        __syncthreads();
    }
    if (t < nb) g_blocksums[t] = sh[t] - v;    // exclusive
}

__global__ void k_scan3(int n) {               // final exclusive scan + cursors
    __shared__ int sh[512];
    int i = blockIdx.x * 512 + threadIdx.x;
    int v = (i < n) ? g_cnt[i] : 0;
    sh[threadIdx.x] = v;
    __syncthreads();
    for (int off = 1; off < 512; off <<= 1) {
        int tmp = (threadIdx.x >= off) ? sh[threadIdx.x - off] : 0;
        __syncthreads();
        sh[threadIdx.x] += tmp;
        __syncthreads();
    }
    int excl = sh[threadIdx.x] - v + g_blocksums[blockIdx.x];
    if (i < n) { g_rowstart[i] = excl; g_cursor[i] = excl; }
    if (i == n - 1) g_rowstart[n] = excl + v;
}

// ---------------- K5: fill CSR columns ----------------
__global__ void k_fill(const int* __restrict__ ei, int E, int TE, int N) {
    int e = blockIdx.x * blockDim.x + threadIdx.x;
    if (e >= TE) return;
    int s, d;
    if (e < E) { s = clampN(__ldg(ei + e), N); d = clampN(__ldg(ei + E + e), N); }
    else       { s = d = e - E; }
    int pos = atomicAdd(&g_cursor[d], 1);
    g_col[pos] = s;
}

// ---------------- K6: gather-aggregate, one warp per dst node ----------------
// softmax without max-subtraction (|e| <~ 10, exp safe; ratio identical)
__global__ __launch_bounds__(256) void k_aggregate(const float* __restrict__ bias,
                                                   float* __restrict__ out, int N) {
    int warp = (int)((blockIdx.x * (unsigned)blockDim.x + threadIdx.x) >> 5);
    if (warp >= N) return;
    int lane = threadIdx.x & 31;
    int head = lane >> 3;

    int start = g_rowstart[warp];
    int end   = g_rowstart[warp + 1];
    float4 ad4 = *(const float4*)(g_adst + (size_t)warp * 4);
    float adst_h = (head == 0) ? ad4.x : (head == 1) ? ad4.y : (head == 2) ? ad4.z : ad4.w;

    // pass 1: denominators (all 4 heads, lanes split edges, warp-reduce)
    float4 den = {0.f, 0.f, 0.f, 0.f};
    for (int i = start + lane; i < end; i += 32) {
        int s = g_col[i];
        float4 as4 = *(const float4*)(g_asrc + (size_t)s * 4);
        den.x += __expf(lrelu(as4.x + ad4.x));
        den.y += __expf(lrelu(as4.y + ad4.y));
        den.z += __expf(lrelu(as4.z + ad4.z));
        den.w += __expf(lrelu(as4.w + ad4.w));
    }
#pragma unroll
    for (int off = 16; off; off >>= 1) {
        den.x += __shfl_xor_sync(0xffffffffu, den.x, off);
        den.y += __shfl_xor_sync(0xffffffffu, den.y, off);
        den.z += __shfl_xor_sync(0xffffffffu, den.z, off);
        den.w += __shfl_xor_sync(0xffffffffu, den.w, off);
    }
    float den_h = (head == 0) ? den.x : (head == 1) ? den.y : (head == 2) ? den.z : den.w;
    float inv_den = 1.0f / (den_h + 1e-16f);

    // pass 2: weighted gather, accumulate in registers
    float acc[8];
#pragma unroll
    for (int j = 0; j < 8; j++) acc[j] = 0.f;
    const int cbase = lane * 8;

    int i = start;
    int s = (i < end) ? g_col[i] : 0;
    for (; i < end; i++) {
        int s_next = (i + 1 < end) ? g_col[i + 1] : 0;   // prefetch
        float a_s = g_asrc[(size_t)s * 4 + head];
        float alpha = __expf(lrelu(a_s + adst_h)) * inv_den;
        const float4* hp = (const float4*)(g_h + (size_t)s * HC + cbase);
        float4 h0 = hp[0], h1 = hp[1];
        acc[0] += alpha * h0.x; acc[1] += alpha * h0.y;
        acc[2] += alpha * h0.z; acc[3] += alpha * h0.w;
        acc[4] += alpha * h1.x; acc[5] += alpha * h1.y;
        acc[6] += alpha * h1.z; acc[7] += alpha * h1.w;
        s = s_next;
    }

    const float4* bp = (const float4*)(bias + cbase);
    float4 b0 = __ldg(bp), b1 = __ldg(bp + 1);
    float4 o0 = {acc[0] + b0.x, acc[1] + b0.y, acc[2] + b0.z, acc[3] + b0.w};
    float4 o1 = {acc[4] + b1.x, acc[5] + b1.y, acc[6] + b1.z, acc[7] + b1.w};
    float4* op = (float4*)(out + (size_t)warp * HC + cbase);
    op[0] = o0;
    op[1] = o1;
}

// ---------------- launch ----------------
extern "C" void kernel_launch(void* const* d_in, const int* in_sizes, int n_in,
                              void* d_out, int out_size) {
    const float* x       = (const float*)d_in[0];
    const int*   ei      = (const int*)d_in[1];     // int32
    const float* W       = (const float*)d_in[2];
    const float* att_src = (const float*)d_in[3];
    const float* att_dst = (const float*)d_in[4];
    const float* bias    = (const float*)d_in[5];
    float*       out     = (float*)d_out;

    const int N  = in_sizes[0] / IN_CH;   // 50000
    const int E  = in_sizes[1] / 2;       // 800000
    const int TE = E + N;                 // 850000
    const int NH = N * HEADS;
    const int NB512 = (N + 511) / 512;    // 98

    k_setup<<<(N + 255) / 256, 256>>>(N);
    k_gemm<<<(N + 63) / 64, 256>>>(x, W, N);
    k_logits<<<(NH + 255) / 256, 256>>>(att_src, att_dst, N);
    k_hist<<<(E + 255) / 256, 256>>>(ei, E, N);
    k_scan1<<<NB512, 512>>>(N);
    k_scan2<<<1, 128>>>(NB512);
    k_scan3<<<NB512, 512>>>(N);
    k_fill<<<(TE + 255) / 256, 256>>>(ei, E, TE, N);
    long long agg_threads = (long long)N * 32;
    k_aggregate<<<(unsigned)((agg_threads + 255) / 256), 256>>>(bias, out, N);
}

// round 7
// speedup vs baseline: 1.9046x; 1.0508x over previous
#include <cuda_runtime.h>
#include <cuda_fp16.h>

typedef unsigned long long ull;

#define NN 50000
#define IN_CH 128
#define OUT_CH 64
#define HEADS 4
#define HC 256            // HEADS*OUT_CH
#define MAX_E 800000
#define MAX_TE (MAX_E + NN)
#define NEG_SLOPE 0.2f

// ---------------- scratch (allocation-free) ----------------
__device__ float  g_h[(size_t)NN * HC];        // 51.2 MB (fp32, logits path)
__device__ __half g_h16[(size_t)NN * HC];      // 25.6 MB (fp16, gather path)
__device__ float  g_asrc[NN * HEADS];
__device__ float  g_adst[NN * HEADS];
__device__ int    g_cnt[NN];                   // in-degree histogram
__device__ int    g_rowstart[NN + 1];          // CSR row pointers (by dst)
__device__ int    g_cursor[NN];                // fill cursors
__device__ int    g_blocksums[128];
__device__ int    g_col[MAX_TE];               // src per CSR slot

// ---------------- helpers ----------------
__device__ __forceinline__ float lrelu(float v) {
    return v >= 0.f ? v : NEG_SLOPE * v;
}
__device__ __forceinline__ int clampN(int v, int N) {
    v = v < 0 ? 0 : v;
    return v >= N ? N - 1 : v;
}
__device__ __forceinline__ ull splat2(float x) {
    ull r;
    asm("mov.b64 %0, {%1, %1};" : "=l"(r) : "r"(__float_as_uint(x)));
    return r;
}
__device__ __forceinline__ void fma2(ull& d, ull a, ull b) {
    asm("fma.rn.f32x2 %0, %1, %2, %0;" : "+l"(d) : "l"(a), "l"(b));
}

// ---------------- K0: init degree counters (1 = self-loop) ----------------
__global__ void k_setup(int N) {
    int i = blockIdx.x * blockDim.x + threadIdx.x;
    if (i < N) g_cnt[i] = 1;
}

// ---------------- K1: h = x @ W  (fp32 FFMA2) + fp16 shadow copy ----------------
__global__ __launch_bounds__(256) void k_gemm(const float* __restrict__ x,
                                              const float* __restrict__ W,
                                              int N) {
    __shared__ float xs[64 * IN_CH];   // 32 KB
    const int tid = threadIdx.x;
    const int col_t = tid & 31;
    const int row_g = tid >> 5;
    const int block_row = blockIdx.x * 64;

    const float4* x4 = (const float4*)x;
    float4* xs4 = (float4*)xs;
#pragma unroll
    for (int i = 0; i < 8; i++) {
        int idx = tid + 256 * i;
        int r = block_row + (idx >> 5);
        int rc = r < N ? r : N - 1;
        xs4[idx] = x4[(size_t)rc * 32 + (idx & 31)];
    }
    __syncthreads();

    ull acc[8][4];
#pragma unroll
    for (int i = 0; i < 8; i++)
#pragma unroll
        for (int j = 0; j < 4; j++) acc[i][j] = 0ull;

    const float* xrow = xs + row_g * 8 * IN_CH;
    const int wcol = col_t * 2;

#pragma unroll 4
    for (int k = 0; k < IN_CH; k++) {
        ull w0 = __ldg((const ull*)&W[k * HC + 0 * 64 + wcol]);
        ull w1 = __ldg((const ull*)&W[k * HC + 1 * 64 + wcol]);
        ull w2 = __ldg((const ull*)&W[k * HC + 2 * 64 + wcol]);
        ull w3 = __ldg((const ull*)&W[k * HC + 3 * 64 + wcol]);
#pragma unroll
        for (int i = 0; i < 8; i++) {
            ull xx = splat2(xrow[i * IN_CH + k]);
            fma2(acc[i][0], xx, w0);
            fma2(acc[i][1], xx, w1);
            fma2(acc[i][2], xx, w2);
            fma2(acc[i][3], xx, w3);
        }
    }

#pragma unroll
    for (int i = 0; i < 8; i++) {
        int r = block_row + row_g * 8 + i;
        if (r < N) {
#pragma unroll
            for (int jj = 0; jj < 4; jj++) {
                ull a = acc[i][jj];
                *(ull*)&g_h[(size_t)r * HC + jj * 64 + wcol] = a;
                float lo = __uint_as_float((unsigned)a);
                float hi = __uint_as_float((unsigned)(a >> 32));
                *(__half2*)&g_h16[(size_t)r * HC + jj * 64 + wcol] =
                    __floats2half2_rn(lo, hi);
            }
        }
    }
}

// ---------------- K2: per-node attention logits (fp32 h) ----------------
__global__ void k_logits(const float* __restrict__ att_src,
                         const float* __restrict__ att_dst, int N) {
    int t = blockIdx.x * blockDim.x + threadIdx.x;
    if (t >= N * HEADS) return;
    int n = t >> 2, hh = t & 3;
    const float4* hv = (const float4*)(g_h + (size_t)n * HC + hh * OUT_CH);
    const float4* as = (const float4*)(att_src + hh * OUT_CH);
    const float4* ad = (const float4*)(att_dst + hh * OUT_CH);
    float s = 0.f, d = 0.f;
#pragma unroll
    for (int c = 0; c < 16; c++) {
        float4 h4 = hv[c];
        float4 a4 = __ldg(&as[c]);
        float4 b4 = __ldg(&ad[c]);
        s += h4.x * a4.x + h4.y * a4.y + h4.z * a4.z + h4.w * a4.w;
        d += h4.x * b4.x + h4.y * b4.y + h4.z * b4.z + h4.w * b4.w;
    }
    g_asrc[t] = s;
    g_adst[t] = d;
}

// ---------------- K3: in-degree histogram over dst ----------------
__global__ void k_hist(const int* __restrict__ ei, int E, int N) {
    int e = blockIdx.x * blockDim.x + threadIdx.x;
    if (e >= E) return;
    int d = clampN(__ldg(ei + E + e), N);
    atomicAdd(&g_cnt[d], 1);
}

// ---------------- K4a/b/c: exclusive scan of g_cnt -> g_rowstart ----------------
__global__ void k_scan1(int n) {               // per-block sums
    __shared__ int sh[512];
    int i = blockIdx.x * 512 + threadIdx.x;
    sh[threadIdx.x] = (i < n) ? g_cnt[i] : 0;
    __syncthreads();
    for (int off = 256; off > 0; off >>= 1) {
        if (threadIdx.x < off) sh[threadIdx.x] += sh[threadIdx.x + off];
        __syncthreads();
    }
    if (threadIdx.x == 0) g_blocksums[blockIdx.x] = sh[0];
}

__global__ void k_scan2(int nb) {              // scan of block sums (1 block)
    __shared__ int sh[128];
    int t = threadIdx.x;
    int v = (t < nb) ? g_blocksums[t] : 0;
    sh[t] = v;
    __syncthreads();
    for (int off = 1; off < 128; off <<= 1) {
        int tmp = (t >= off) ? sh[t - off] : 0;
        __syncthreads();
        sh[t] += tmp;
        __syncthreads();
    }
    if (t < nb) g_blocksums[t] = sh[t] - v;    // exclusive
}

__global__ void k_scan3(int n) {               // final exclusive scan + cursors
    __shared__ int sh[512];
    int i = blockIdx.x * 512 + threadIdx.x;
    int v = (i < n) ? g_cnt[i] : 0;
    sh[threadIdx.x] = v;
    __syncthreads();
    for (int off = 1; off < 512; off <<= 1) {
        int tmp = (threadIdx.x >= off) ? sh[threadIdx.x - off] : 0;
        __syncthreads();
        sh[threadIdx.x] += tmp;
        __syncthreads();
    }
    int excl = sh[threadIdx.x] - v + g_blocksums[blockIdx.x];
    if (i < n) { g_rowstart[i] = excl; g_cursor[i] = excl; }
    if (i == n - 1) g_rowstart[n] = excl + v;
}

// ---------------- K5: fill CSR columns ----------------
__global__ void k_fill(const int* __restrict__ ei, int E, int TE, int N) {
    int e = blockIdx.x * blockDim.x + threadIdx.x;
    if (e >= TE) return;
    int s, d;
    if (e < E) { s = clampN(__ldg(ei + e), N); d = clampN(__ldg(ei + E + e), N); }
    else       { s = d = e - E; }
    int pos = atomicAdd(&g_cursor[d], 1);
    g_col[pos] = s;
}

// ---------------- K6: gather-aggregate, one warp per dst node ----------------
// softmax without max-subtraction (|e| <~ 10, exp safe; ratio identical)
// pass 2 gathers fp16 h (half the bytes), accumulates fp32
__global__ __launch_bounds__(256) void k_aggregate(const float* __restrict__ bias,
                                                   float* __restrict__ out, int N) {
    int warp = (int)((blockIdx.x * (unsigned)blockDim.x + threadIdx.x) >> 5);
    if (warp >= N) return;
    int lane = threadIdx.x & 31;
    int head = lane >> 3;

    int start = g_rowstart[warp];
    int end   = g_rowstart[warp + 1];
    float4 ad4 = *(const float4*)(g_adst + (size_t)warp * 4);
    float adst_h = (head == 0) ? ad4.x : (head == 1) ? ad4.y : (head == 2) ? ad4.z : ad4.w;

    // pass 1: denominators (all 4 heads, lanes split edges, warp-reduce)
    float4 den = {0.f, 0.f, 0.f, 0.f};
    for (int i = start + lane; i < end; i += 32) {
        int s = g_col[i];
        float4 as4 = *(const float4*)(g_asrc + (size_t)s * 4);
        den.x += __expf(lrelu(as4.x + ad4.x));
        den.y += __expf(lrelu(as4.y + ad4.y));
        den.z += __expf(lrelu(as4.z + ad4.z));
        den.w += __expf(lrelu(as4.w + ad4.w));
    }
#pragma unroll
    for (int off = 16; off; off >>= 1) {
        den.x += __shfl_xor_sync(0xffffffffu, den.x, off);
        den.y += __shfl_xor_sync(0xffffffffu, den.y, off);
        den.z += __shfl_xor_sync(0xffffffffu, den.z, off);
        den.w += __shfl_xor_sync(0xffffffffu, den.w, off);
    }
    float den_h = (head == 0) ? den.x : (head == 1) ? den.y : (head == 2) ? den.z : den.w;
    float inv_den = 1.0f / (den_h + 1e-16f);

    // pass 2: weighted fp16 gather, accumulate in fp32 registers
    float acc[8];
#pragma unroll
    for (int j = 0; j < 8; j++) acc[j] = 0.f;
    const int cbase = lane * 8;

    int i = start;
    int s = (i < end) ? g_col[i] : 0;
    for (; i < end; i++) {
        int s_next = (i + 1 < end) ? g_col[i + 1] : 0;   // prefetch
        float a_s = g_asrc[(size_t)s * 4 + head];
        float alpha = __expf(lrelu(a_s + adst_h)) * inv_den;
        uint4 hv = *(const uint4*)(g_h16 + (size_t)s * HC + cbase);  // 8 halves
        float2 f0 = __half22float2(*(__half2*)&hv.x);
        float2 f1 = __half22float2(*(__half2*)&hv.y);
        float2 f2 = __half22float2(*(__half2*)&hv.z);
        float2 f3 = __half22float2(*(__half2*)&hv.w);
        acc[0] += alpha * f0.x; acc[1] += alpha * f0.y;
        acc[2] += alpha * f1.x; acc[3] += alpha * f1.y;
        acc[4] += alpha * f2.x; acc[5] += alpha * f2.y;
        acc[6] += alpha * f3.x; acc[7] += alpha * f3.y;
        s = s_next;
    }

    const float4* bp = (const float4*)(bias + cbase);
    float4 b0 = __ldg(bp), b1 = __ldg(bp + 1);
    float4 o0 = {acc[0] + b0.x, acc[1] + b0.y, acc[2] + b0.z, acc[3] + b0.w};
    float4 o1 = {acc[4] + b1.x, acc[5] + b1.y, acc[6] + b1.z, acc[7] + b1.w};
    float4* op = (float4*)(out + (size_t)warp * HC + cbase);
    op[0] = o0;
    op[1] = o1;
}

// ---------------- launch ----------------
extern "C" void kernel_launch(void* const* d_in, const int* in_sizes, int n_in,
                              void* d_out, int out_size) {
    const float* x       = (const float*)d_in[0];
    const int*   ei      = (const int*)d_in[1];     // int32
    const float* W       = (const float*)d_in[2];
    const float* att_src = (const float*)d_in[3];
    const float* att_dst = (const float*)d_in[4];
    const float* bias    = (const float*)d_in[5];
    float*       out     = (float*)d_out;

    const int N  = in_sizes[0] / IN_CH;   // 50000
    const int E  = in_sizes[1] / 2;       // 800000
    const int TE = E + N;                 // 850000
    const int NH = N * HEADS;
    const int NB512 = (N + 511) / 512;    // 98

    k_setup<<<(N + 255) / 256, 256>>>(N);
    k_gemm<<<(N + 63) / 64, 256>>>(x, W, N);
    k_logits<<<(NH + 255) / 256, 256>>>(att_src, att_dst, N);
    k_hist<<<(E + 255) / 256, 256>>>(ei, E, N);
    k_scan1<<<NB512, 512>>>(N);
    k_scan2<<<1, 128>>>(NB512);
    k_scan3<<<NB512, 512>>>(N);
    k_fill<<<(TE + 255) / 256, 256>>>(ei, E, TE, N);
    long long agg_threads = (long long)N * 32;
    k_aggregate<<<(unsigned)((agg_threads + 255) / 256), 256>>>(bias, out, N);
}